// round 16
// baseline (speedup 1.0000x reference)
#include <cuda_runtime.h>
#include <cuda_bf16.h>
#include <cuda_fp16.h>
#include <math.h>
#include <stdint.h>

#define Nn 100000
#define Ee 1600000
#define INDIM 128
#define HD 128

// ---------------- scratch (device globals; no allocation allowed) ----------
__device__ __half g_xlh[(size_t)Nn * HD];    // x @ W_l, fp16
__device__ float g_a1[Nn * 4];
__device__ float g_a2[Nn * 4];
__device__ int   g_deg[Nn];
__device__ int   g_rowptr[Nn + 1];
__device__ int   g_cursor[Nn];
__device__ int   g_ecol[Ee];                 // CSR-ordered source col per edge
__device__ int   g_scan[100352];             // 98 * 1024
__device__ int   g_bsums[128];
__device__ int   g_boffs[128];
// B = W^T split to bf16 hi/lo, layout [n(256: Wl cols then Wr cols)][k(128)]
__device__ __nv_bfloat16 g_Bh[2 * 128 * 128];
__device__ __nv_bfloat16 g_Bl[2 * 128 * 128];

// ======================= helpers ============================================
__device__ __forceinline__ uint32_t smem_u32(const void* p) {
    uint32_t a;
    asm("{ .reg .u64 t; cvta.to.shared.u64 t, %1; cvt.u32.u64 %0, t; }"
        : "=r"(a) : "l"(p));
    return a;
}

__device__ __forceinline__ void ldsm4(uint32_t* r, uint32_t addr) {
    asm volatile("ldmatrix.sync.aligned.m8n8.x4.shared.b16 {%0,%1,%2,%3}, [%4];"
                 : "=r"(r[0]), "=r"(r[1]), "=r"(r[2]), "=r"(r[3]) : "r"(addr));
}

__device__ __forceinline__ void mma16816(float* c, const uint32_t* a, const uint32_t* b) {
    asm volatile(
        "mma.sync.aligned.m16n8k16.row.col.f32.bf16.bf16.f32 "
        "{%0,%1,%2,%3}, {%4,%5,%6,%7}, {%8,%9}, {%0,%1,%2,%3};"
        : "+f"(c[0]), "+f"(c[1]), "+f"(c[2]), "+f"(c[3])
        : "r"(a[0]), "r"(a[1]), "r"(a[2]), "r"(a[3]), "r"(b[0]), "r"(b[1]));
}

// =============== prep: W^T -> bf16 hi/lo in B-layout [n(256)][k] ============
__global__ void prep_B(const float* __restrict__ Wl, const float* __restrict__ Wr) {
    int idx = blockIdx.x * 256 + threadIdx.x;
    if (idx >= 2 * 128 * 128) return;
    int nt = idx >> 14;
    int n = (idx >> 7) & 127;
    int k = idx & 127;
    const float* W = nt ? Wr : Wl;
    float v = W[k * 128 + n];
    __nv_bfloat16 h = __float2bfloat16(v);
    __nv_bfloat16 l = __float2bfloat16(v - __bfloat162float(h));
    g_Bh[idx] = h;
    g_Bl[idx] = l;
}

// = mma.sync bf16-split GEMM + fused a1/a2: 1024 threads =====================
#define ASM_A_HI 0
#define ASM_A_LO 32768
#define ASM_B_HI 65536
#define ASM_B_LO 131072
#define ASM_AW   196608
#define GSM_TOTAL 200704

__global__ __launch_bounds__(1024, 1) void gemm_tc(const float* __restrict__ x,
                                                   const float* __restrict__ bias,
                                                   const float* __restrict__ a1w,
                                                   const float* __restrict__ a2w,
                                                   float* __restrict__ out) {
    extern __shared__ char smem[];
    const uint32_t sb = smem_u32(smem);

    const int tid = threadIdx.x;
    const int w = tid >> 5;
    const int lane = tid & 31;
    const int row0 = blockIdx.x * 128;

    union Pack4 { __nv_bfloat16 b[4]; uint64_t u; };

    // ---- aw: stage a1w/a2w (each 128x4 fp32) -------------------------------
    float* awf = (float*)(smem + ASM_AW);
    if (tid < 512) {
        awf[tid] = a1w[tid];
        awf[512 + tid] = a2w[tid];
    }

    // ---- A: load fp32 X tile once, split hi/lo bf16, swizzled store --------
    for (int idx = tid; idx < 128 * 32; idx += 1024) {  // one float4 each
        int r = idx >> 5;
        int c4 = idx & 31;                               // float4 index (k = c4*4)
        float4 v = make_float4(0.f, 0.f, 0.f, 0.f);
        int gr = row0 + r;
        if (gr < Nn) v = ((const float4*)x)[(size_t)gr * 32 + c4];
        float vv[4] = {v.x, v.y, v.z, v.w};
        Pack4 ph, pl;
#pragma unroll
        for (int j = 0; j < 4; j++) {
            __nv_bfloat16 h = __float2bfloat16(vv[j]);
            ph.b[j] = h;
            pl.b[j] = __float2bfloat16(vv[j] - __bfloat162float(h));
        }
        int chunk = c4 >> 1;                             // 16B chunk (8 bf16)
        int sub = (c4 & 1) * 8;
        uint32_t off = (uint32_t)(r * 256 + ((chunk ^ (r & 7)) << 4) + sub);
        *(uint64_t*)(smem + ASM_A_HI + off) = ph.u;
        *(uint64_t*)(smem + ASM_A_LO + off) = pl.u;
    }

    // ---- B: copy full pre-split bf16 [256 n][128 k] tile, swizzled ---------
    for (int idx = tid; idx < 256 * 16; idx += 1024) {  // 16B chunks
        int n = idx >> 4;
        int c = idx & 15;
        uint32_t off = (uint32_t)(n * 256 + ((c ^ (n & 7)) << 4));
        size_t src = (size_t)n * 128 + c * 8;
        *(uint4*)(smem + ASM_B_HI + off) = *(const uint4*)&g_Bh[src];
        *(uint4*)(smem + ASM_B_LO + off) = *(const uint4*)&g_Bl[src];
    }
    __syncthreads();

    // ---- compute: 32 warps in 8(m) x 4(n), warp tile 16(m) x 64(n) ---------
    const int wm = w & 7, wn = w >> 3;
    const int mb = wm * 16, nb = wn * 64;                // nb over 256 cols
    const int q = lane >> 3, r8 = lane & 7;

    float acc[8][4];
#pragma unroll
    for (int j = 0; j < 8; j++)
#pragma unroll
        for (int c = 0; c < 4; c++) acc[j][c] = 0.f;

#pragma unroll
    for (int kt = 0; kt < 8; kt++) {                    // K = 8 x 16
        int kc = kt * 2;
        uint32_t Ah[4], Al[4];
        {
            int row = mb + (q & 1) * 8 + r8;
            int ch = kc + (q >> 1);
            uint32_t off = (uint32_t)(row * 256 + ((ch ^ (row & 7)) << 4));
            ldsm4(Ah, sb + ASM_A_HI + off);
            ldsm4(Al, sb + ASM_A_LO + off);
        }
#pragma unroll
        for (int p = 0; p < 4; p++) {
            uint32_t Bh[4], Bl[4];
            int row = nb + p * 16 + (q >> 1) * 8 + r8;
            int ch = kc + (q & 1);
            uint32_t off = (uint32_t)(row * 256 + ((ch ^ (row & 7)) << 4));
            ldsm4(Bh, sb + ASM_B_HI + off);
            ldsm4(Bl, sb + ASM_B_LO + off);
#pragma unroll
            for (int hf = 0; hf < 2; hf++)
                mma16816(acc[p * 2 + hf], Ah, &Bh[hf * 2]);
#pragma unroll
            for (int hf = 0; hf < 2; hf++)
                mma16816(acc[p * 2 + hf], Al, &Bh[hf * 2]);
#pragma unroll
            for (int hf = 0; hf < 2; hf++)
                mma16816(acc[p * 2 + hf], Ah, &Bl[hf * 2]);
        }
    }

    // ---- epilogue: cols<128 -> g_xlh (fp16), else out+bias (fp32) ----------
    const int g = lane >> 2, t = lane & 3;
#pragma unroll
    for (int ni = 0; ni < 8; ni++) {
        int col = nb + ni * 8 + t * 2;                  // 0..255
        bool is_out = col >= 128;
        int oc = col & 127;
        float b0 = 0.f, b1 = 0.f;
        if (is_out) { b0 = bias[oc]; b1 = bias[oc + 1]; }
        float* cc = acc[ni];
        int r0 = row0 + mb + g;
        if (r0 < Nn) {
            if (!is_out)
                *(__half2*)&g_xlh[(size_t)r0 * HD + oc] = __floats2half2_rn(cc[0], cc[1]);
            else
                *(float2*)&out[(size_t)r0 * HD + oc] = make_float2(cc[0] + b0, cc[1] + b1);
        }
        int r1 = r0 + 8;
        if (r1 < Nn) {
            if (!is_out)
                *(__half2*)&g_xlh[(size_t)r1 * HD + oc] = __floats2half2_rn(cc[2], cc[3]);
            else
                *(float2*)&out[(size_t)r1 * HD + oc] = make_float2(cc[2] + b0, cc[3] + b1);
        }
    }

    // ---- fused a1/a2: 8 threads per row, 16 k each; A = Ah+Al (~fp32) ------
    {
        const float* aw1 = awf;            // [k][h] fp32
        const float* aw2 = awf + 512;
        int r = tid >> 3, sub = tid & 7;
        float a1acc[4] = {0.f, 0.f, 0.f, 0.f};
        float a2acc[4] = {0.f, 0.f, 0.f, 0.f};
#pragma unroll
        for (int cc = 0; cc < 2; cc++) {
            int ch = sub * 2 + cc;
            uint32_t off = (uint32_t)(r * 256 + ((ch ^ (r & 7)) << 4));
#pragma unroll
            for (int jj = 0; jj < 4; jj++) {
                uint32_t hv = *(const uint32_t*)(smem + ASM_A_HI + off + jj * 4);
                uint32_t lv = *(const uint32_t*)(smem + ASM_A_LO + off + jj * 4);
                float2 fh = __bfloat1622float2(*(const __nv_bfloat162*)&hv);
                float2 fl = __bfloat1622float2(*(const __nv_bfloat162*)&lv);
                float x0 = fh.x + fl.x;
                float x1 = fh.y + fl.y;
                int k = ch * 8 + jj * 2;
#pragma unroll
                for (int h = 0; h < 4; h++) {
                    a1acc[h] += x0 * aw1[k * 4 + h] + x1 * aw1[(k + 1) * 4 + h];
                    a2acc[h] += x0 * aw2[k * 4 + h] + x1 * aw2[(k + 1) * 4 + h];
                }
            }
        }
#pragma unroll
        for (int o = 4; o; o >>= 1)
#pragma unroll
            for (int h = 0; h < 4; h++) {
                a1acc[h] += __shfl_xor_sync(0xffffffffu, a1acc[h], o);
                a2acc[h] += __shfl_xor_sync(0xffffffffu, a2acc[h], o);
            }
        int gr = row0 + r;
        if (sub == 0 && gr < Nn) {
            ((float4*)g_a1)[gr] = make_float4(a1acc[0], a1acc[1], a1acc[2], a1acc[3]);
            ((float4*)g_a2)[gr] = make_float4(a2acc[0], a2acc[1], a2acc[2], a2acc[3]);
        }
    }
}

// ---------------- CSR construction -----------------------------------------
__global__ void zero_deg() {
    int i = blockIdx.x * 1024 + threadIdx.x;
    if (i < Nn) g_deg[i] = 0;
}

__global__ void hist_kernel(const int* __restrict__ row) {
    int e = blockIdx.x * 256 + threadIdx.x;
    if (e < Ee) atomicAdd(&g_deg[row[e]], 1);
}

__global__ void scan_block() {
    __shared__ int s[1024];
    int i = blockIdx.x * 1024 + threadIdx.x;
    int v = (i < Nn) ? g_deg[i] : 0;
    s[threadIdx.x] = v;
    __syncthreads();
#pragma unroll
    for (int off = 1; off < 1024; off <<= 1) {
        int t = (threadIdx.x >= off) ? s[threadIdx.x - off] : 0;
        __syncthreads();
        s[threadIdx.x] += t;
        __syncthreads();
    }
    g_scan[i] = s[threadIdx.x];
    if (threadIdx.x == 1023) g_bsums[blockIdx.x] = s[1023];
}

__global__ void scan_top() {
    __shared__ int s[128];
    int t = threadIdx.x;
    int v = (t < 98) ? g_bsums[t] : 0;
    s[t] = v;
    __syncthreads();
#pragma unroll
    for (int off = 1; off < 128; off <<= 1) {
        int u = (t >= off) ? s[t - off] : 0;
        __syncthreads();
        s[t] += u;
        __syncthreads();
    }
    g_boffs[t] = s[t] - v;
}

__global__ void scan_finalize() {
    int i = blockIdx.x * 1024 + threadIdx.x;
    if (i < Nn) {
        int ex = g_scan[i] - g_deg[i] + g_boffs[blockIdx.x];
        g_rowptr[i] = ex;
        g_cursor[i] = ex;
    } else if (i == Nn) {
        g_rowptr[Nn] = Ee;
    }
}

// scatter col values directly into CSR order (no edge-id indirection)
__global__ void scatter_kernel(const int* __restrict__ row, const int* __restrict__ col) {
    int e = blockIdx.x * 256 + threadIdx.x;
    if (e < Ee) {
        int pos = atomicAdd(&g_cursor[row[e]], 1);
        g_ecol[pos] = col[e];
    }
}

// ------ fused attention + softmax + SpMM: single pass, one warp per row -----
// softmax(z) == softmax(z - m); logits are O(10) so exp() cannot overflow fp32.
__global__ void aggregate_kernel(float* __restrict__ out) {
    int warp = (blockIdx.x * blockDim.x + threadIdx.x) >> 5;
    int lane = threadIdx.x & 31;
    if (warp >= Nn) return;
    int start = g_rowptr[warp];
    int end   = g_rowptr[warp + 1];
    if (start == end) return;                        // out already = x_r + bias

    int h = lane >> 3;                               // head for this lane group
    float a1h = g_a1[warp * 4 + h];
    const size_t lo4 = (size_t)lane * 4;

    float4 acc = make_float4(0.f, 0.f, 0.f, 0.f);
    float sumh = 0.f;

    int i = start;
    // 4-edge batches: front-batch all loads for MLP=4 on the gather chain
    for (; i + 4 <= end; i += 4) {
        int c0 = g_ecol[i + 0];
        int c1 = g_ecol[i + 1];
        int c2 = g_ecol[i + 2];
        int c3 = g_ecol[i + 3];
        float z0 = a1h + __ldg(&g_a2[c0 * 4 + h]);
        float z1 = a1h + __ldg(&g_a2[c1 * 4 + h]);
        float z2 = a1h + __ldg(&g_a2[c2 * 4 + h]);
        float z3 = a1h + __ldg(&g_a2[c3 * 4 + h]);
        uint2 p0 = *(const uint2*)&g_xlh[(size_t)c0 * HD + lo4];
        uint2 p1 = *(const uint2*)&g_xlh[(size_t)c1 * HD + lo4];
        uint2 p2 = *(const uint2*)&g_xlh[(size_t)c2 * HD + lo4];
        uint2 p3 = *(const uint2*)&g_xlh[(size_t)c3 * HD + lo4];
        z0 = z0 > 0.f ? z0 : 0.2f * z0;
        z1 = z1 > 0.f ? z1 : 0.2f * z1;
        z2 = z2 > 0.f ? z2 : 0.2f * z2;
        z3 = z3 > 0.f ? z3 : 0.2f * z3;
        float w0 = __expf(z0), w1 = __expf(z1), w2 = __expf(z2), w3 = __expf(z3);
        sumh += (w0 + w1) + (w2 + w3);
        {
            float2 a = __half22float2(*(const __half2*)&p0.x);
            float2 b = __half22float2(*(const __half2*)&p0.y);
            acc.x += w0 * a.x; acc.y += w0 * a.y; acc.z += w0 * b.x; acc.w += w0 * b.y;
        }
        {
            float2 a = __half22float2(*(const __half2*)&p1.x);
            float2 b = __half22float2(*(const __half2*)&p1.y);
            acc.x += w1 * a.x; acc.y += w1 * a.y; acc.z += w1 * b.x; acc.w += w1 * b.y;
        }
        {
            float2 a = __half22float2(*(const __half2*)&p2.x);
            float2 b = __half22float2(*(const __half2*)&p2.y);
            acc.x += w2 * a.x; acc.y += w2 * a.y; acc.z += w2 * b.x; acc.w += w2 * b.y;
        }
        {
            float2 a = __half22float2(*(const __half2*)&p3.x);
            float2 b = __half22float2(*(const __half2*)&p3.y);
            acc.x += w3 * a.x; acc.y += w3 * a.y; acc.z += w3 * b.x; acc.w += w3 * b.y;
        }
    }
    for (; i < end; i++) {
        int c = g_ecol[i];
        float z = a1h + __ldg(&g_a2[c * 4 + h]);
        z = z > 0.f ? z : 0.2f * z;
        float w = __expf(z);
        sumh += w;
        uint2 pv = *(const uint2*)&g_xlh[(size_t)c * HD + lo4];
        float2 va = __half22float2(*(const __half2*)&pv.x);
        float2 vb = __half22float2(*(const __half2*)&pv.y);
        acc.x += w * va.x; acc.y += w * va.y;
        acc.z += w * vb.x; acc.w += w * vb.y;
    }
    float inv = 1.0f / sumh;
    float4* op = (float4*)out + (size_t)warp * 32 + lane;
    float4 t = *op;                                  // holds x@W_r + bias
    t.x += acc.x * inv; t.y += acc.y * inv;
    t.z += acc.z * inv; t.w += acc.w * inv;
    *op = t;
}

// ---------------- launch ----------------------------------------------------
extern "C" void kernel_launch(void* const* d_in, const int* in_sizes, int n_in,
                              void* d_out, int out_size) {
    const float* x    = (const float*)d_in[0];
    const int*   row  = (const int*)d_in[1];
    const int*   col  = (const int*)d_in[2];
    const float* Wl   = (const float*)d_in[3];
    const float* Wr   = (const float*)d_in[4];
    const float* a1w  = (const float*)d_in[5];
    const float* a2w  = (const float*)d_in[6];
    const float* bias = (const float*)d_in[7];
    float* out = (float*)d_out;
    (void)in_sizes; (void)n_in; (void)out_size;

    cudaFuncSetAttribute(gemm_tc, cudaFuncAttributeMaxDynamicSharedMemorySize, GSM_TOTAL);

    // single stream (known-good); gemm_tc kept as 4th launch for ncu window
    zero_deg<<<98, 1024>>>();
    prep_B<<<128, 256>>>(Wl, Wr);
    hist_kernel<<<6250, 256>>>(row);
    gemm_tc<<<782, 1024, GSM_TOTAL>>>(x, bias, a1w, a2w, out);
    scan_block<<<98, 1024>>>();
    scan_top<<<1, 128>>>();
    scan_finalize<<<98, 1024>>>();
    scatter_kernel<<<6250, 256>>>(row, col);
    aggregate_kernel<<<12500, 256>>>(out);
}